// round 3
// baseline (speedup 1.0000x reference)
#include <cuda_runtime.h>

#define Bsz 2048
#define Tsz 512
#define Asz 32
#define Hsz 16

typedef unsigned long long u64;

__device__ __forceinline__ u64 pack2(float lo, float hi) {
    u64 r; asm("mov.b64 %0, {%1, %2};" : "=l"(r) : "f"(lo), "f"(hi)); return r;
}
__device__ __forceinline__ void unpack2(u64 v, float& lo, float& hi) {
    asm("mov.b64 {%0, %1}, %2;" : "=f"(lo), "=f"(hi) : "l"(v));
}
__device__ __forceinline__ u64 fma2(u64 a, u64 b, u64 c) {
    u64 d; asm("fma.rn.f32x2 %0, %1, %2, %3;" : "=l"(d) : "l"(a), "l"(b), "l"(c)); return d;
}
__device__ __forceinline__ u64 add2(u64 a, u64 b) {
    u64 d; asm("add.rn.f32x2 %0, %1, %2;" : "=l"(d) : "l"(a), "l"(b)); return d;
}
__device__ __forceinline__ float sigmoidf_(float x) {
    return __fdividef(1.0f, 1.0f + __expf(-x));
}

// CTA = 128 threads = 4 warps = 2 batch elements.
//   warp 0,1: CONSUMER for elem 0,1 (recurrence: h-part + activations + state)
//   warp 2,3: PRODUCER for elem 0,1 (x-projection pregates, runs 1 step ahead;
//             also batched actor/critic heads every 8 steps)
// Rings (per elem): pgring depth 2, xring depth 2, hring depth 16.
// One __syncthreads per step orders all producer/consumer ring hand-offs.

__global__ void __launch_bounds__(128, 4) lstm_ws_kernel(
    const float* __restrict__ xin, const float* __restrict__ masks,
    const float* __restrict__ h0, const float* __restrict__ c0,
    const float* __restrict__ w_ih, const float* __restrict__ w_hh,
    const float* __restrict__ b_ih, const float* __restrict__ b_hh,
    const float* __restrict__ w_actor, const float* __restrict__ b_actor,
    const float* __restrict__ w_critic, const float* __restrict__ b_critic,
    float* __restrict__ actor, float* __restrict__ critic,
    float* __restrict__ hT, float* __restrict__ cT)
{
    __shared__ __align__(16) float  xring[2][2][32];
    __shared__ __align__(16) float2 pgring[2][2][32];
    __shared__ __align__(16) float  hring[2][16][16];
    __shared__ __align__(16) float  wact_s[32][20];   // padded rows
    __shared__ float wc_s[16];

    const int tid  = threadIdx.x;
    const int w    = tid >> 5;
    const int lane = tid & 31;
    const int j    = lane & 15;
    const bool hi  = lane >= 16;
    const int e    = w & 1;
    const bool is_prod = (w >= 2);
    const int b    = blockIdx.x * 2 + e;

    for (int i = tid; i < Asz * Hsz; i += 128)
        wact_s[i >> 4][i & 15] = w_actor[i];
    if (tid < 16) wc_s[tid] = w_critic[tid];

    const float* xb = xin   + (size_t)b * Tsz * Asz;
    const float* mb = masks + (size_t)b * Tsz;
    float* actb     = actor + (size_t)b * Tsz * Asz;
    float* crb      = critic + (size_t)b * Tsz;

    // ---------------- per-role register state ----------------
    u64 wA2[16], wB2[16];        // producer: w_ih rows lane, 32+lane
    u64 wAh2[8], wBh2[8];        // consumer: w_hh rows lane, 32+lane
    float biasA = 0.f, biasB = 0.f, xreg = 0.f;
    float c = 0.f, h2 = 0.f, m_cur = 0.f;
    const float bact = b_actor[lane];
    const float bcr  = b_critic[0];

    if (is_prod) {
        const int rA = lane, rB = 32 + lane;
#pragma unroll
        for (int k = 0; k < 16; k++) {
            wA2[k] = pack2(w_ih[rA * 32 + 2 * k], w_ih[rA * 32 + 2 * k + 1]);
            wB2[k] = pack2(w_ih[rB * 32 + 2 * k], w_ih[rB * 32 + 2 * k + 1]);
        }
        biasA = b_ih[rA] + b_hh[rA];
        biasB = b_ih[rB] + b_hh[rB];
        xring[e][0][lane] = xb[lane];            // x_0
        xring[e][1][lane] = xb[Asz + lane];      // x_1
        xreg = xb[2 * Asz + lane];               // x_2
    } else {
        const int rA = lane, rB = 32 + lane;
#pragma unroll
        for (int k = 0; k < 8; k++) {
            wAh2[k] = pack2(w_hh[rA * 16 + 2 * k], w_hh[rA * 16 + 2 * k + 1]);
            wBh2[k] = pack2(w_hh[rB * 16 + 2 * k], w_hh[rB * 16 + 2 * k + 1]);
        }
        c = hi ? c0[b * Hsz + j] : 0.0f;
        if (hi) hring[e][15][j] = h0[b * Hsz + j];
        m_cur = mb[0];
    }
    __syncthreads();

    // prologue: producer computes pregate for t=0 into pg slot 0
    if (is_prod) {
        const ulonglong2* xr = reinterpret_cast<const ulonglong2*>(&xring[e][0][0]);
        u64 aA0 = pack2(biasA, 0.f), aA1 = pack2(0.f, 0.f);
        u64 aB0 = pack2(biasB, 0.f), aB1 = pack2(0.f, 0.f);
#pragma unroll
        for (int q = 0; q < 8; q++) {
            const ulonglong2 v = xr[q];
            aA0 = fma2(wA2[2 * q], v.x, aA0); aA1 = fma2(wA2[2 * q + 1], v.y, aA1);
            aB0 = fma2(wB2[2 * q], v.x, aB0); aB1 = fma2(wB2[2 * q + 1], v.y, aB1);
        }
        float l0, h0_, l1, h1_;
        unpack2(add2(aA0, aA1), l0, h0_);
        unpack2(add2(aB0, aB1), l1, h1_);
        pgring[e][0][lane] = make_float2(l0 + h0_, l1 + h1_);
    }
    __syncthreads();

    for (int t = 0; t < Tsz; t++) {
        if (is_prod) {
            // ---- pregate for step t+1 (reads xring slot (t+1)&1 = x_{t+1})
            const ulonglong2* xr = reinterpret_cast<const ulonglong2*>(&xring[e][(t + 1) & 1][0]);
            u64 aA0 = pack2(biasA, 0.f), aA1 = pack2(0.f, 0.f);
            u64 aB0 = pack2(biasB, 0.f), aB1 = pack2(0.f, 0.f);
#pragma unroll
            for (int q = 0; q < 8; q++) {
                const ulonglong2 v = xr[q];
                aA0 = fma2(wA2[2 * q], v.x, aA0); aA1 = fma2(wA2[2 * q + 1], v.y, aA1);
                aB0 = fma2(wB2[2 * q], v.x, aB0); aB1 = fma2(wB2[2 * q + 1], v.y, aB1);
            }
            float l0, h0_, l1, h1_;
            unpack2(add2(aA0, aA1), l0, h0_);
            unpack2(add2(aB0, aB1), l1, h1_);
            pgring[e][(t + 1) & 1][lane] = make_float2(l0 + h0_, l1 + h1_);

            // ---- stage x_{t+2} (slot t&1), refill carry with x_{t+3}
            xring[e][t & 1][lane] = xreg;
            const int t3 = (t + 3 < Tsz) ? t + 3 : Tsz - 1;
            xreg = xb[t3 * Asz + lane];

            // ---- batched heads for steps t-8..t-1
            if ((t & 7) == 0 && t >= 8) {
                const int t0 = t - 8;
                const ulonglong2* wrow = reinterpret_cast<const ulonglong2*>(&wact_s[lane][0]);
                const ulonglong2 w0 = wrow[0], w1 = wrow[1], w2 = wrow[2], w3 = wrow[3];
#pragma unroll
                for (int k = 0; k < 8; k++) {
                    const ulonglong2* hp = reinterpret_cast<const ulonglong2*>(&hring[e][(t0 + k) & 15][0]);
                    u64 a0 = pack2(bact, 0.f), a1 = pack2(0.f, 0.f);
                    a0 = fma2(w0.x, hp[0].x, a0); a1 = fma2(w0.y, hp[0].y, a1);
                    a0 = fma2(w1.x, hp[1].x, a0); a1 = fma2(w1.y, hp[1].y, a1);
                    a0 = fma2(w2.x, hp[2].x, a0); a1 = fma2(w2.y, hp[2].y, a1);
                    a0 = fma2(w3.x, hp[3].x, a0); a1 = fma2(w3.y, hp[3].y, a1);
                    float s0, s1;
                    unpack2(add2(a0, a1), s0, s1);
                    actb[(t0 + k) * Asz + lane] = s0 + s1;
                }
                if (lane < 8) {
                    const int s = t0 + lane;
                    const float* hrow = &hring[e][s & 15][0];
                    float acc = bcr;
#pragma unroll
                    for (int k = 0; k < 16; k++) acc = fmaf(hrow[k], wc_s[k], acc);
                    crb[s] = acc;
                }
            }
        } else {
            // ---- consumer: recurrence step t
            const float m = m_cur;
            const int tn = (t + 1 < Tsz) ? t + 1 : Tsz - 1;
            m_cur = mb[tn];

            const float2 pgv = pgring[e][t & 1][lane];
            const ulonglong2* hr = reinterpret_cast<const ulonglong2*>(&hring[e][(t + 15) & 15][0]);
            u64 hA0 = pack2(0.f, 0.f), hA1 = pack2(0.f, 0.f);
            u64 hB0 = pack2(0.f, 0.f), hB1 = pack2(0.f, 0.f);
#pragma unroll
            for (int q = 0; q < 4; q++) {
                const ulonglong2 v = hr[q];
                hA0 = fma2(wAh2[2 * q], v.x, hA0); hA1 = fma2(wAh2[2 * q + 1], v.y, hA1);
                hB0 = fma2(wBh2[2 * q], v.x, hB0); hB1 = fma2(wBh2[2 * q + 1], v.y, hB1);
            }
            float a0, a1, b0, b1;
            unpack2(add2(hA0, hA1), a0, a1);
            unpack2(add2(hB0, hB1), b0, b1);
            const float gA = fmaf(m, a0 + a1, pgv.x);   // lo: i, hi: f
            const float gB = fmaf(m, b0 + b1, pgv.y);   // lo: g, hi: o

            const float vA = sigmoidf_(gA);
            const float sB = sigmoidf_(hi ? gB : 2.0f * gB);
            const float vB = hi ? sB : fmaf(2.0f, sB, -1.0f);

            const float p  = vA * vB;                         // lo: i*g
            const float ig = __shfl_sync(0xffffffffu, p, j);  // hi fetches i*g

            c = fmaf(vA, c * m, ig);                          // hi lanes: c2 = f*(c*m)+i*g
            const float tc = fmaf(2.0f, sigmoidf_(2.0f * c), -1.0f);
            h2 = vB * tc;                                     // hi lanes: h2 = o*tanh(c2)

            if (hi) hring[e][t & 15][j] = h2;
        }
        __syncthreads();
    }

    // epilogue
    if (is_prod) {
        const int t0 = Tsz - 8;
        const ulonglong2* wrow = reinterpret_cast<const ulonglong2*>(&wact_s[lane][0]);
        const ulonglong2 w0 = wrow[0], w1 = wrow[1], w2 = wrow[2], w3 = wrow[3];
#pragma unroll
        for (int k = 0; k < 8; k++) {
            const ulonglong2* hp = reinterpret_cast<const ulonglong2*>(&hring[e][(t0 + k) & 15][0]);
            u64 a0 = pack2(bact, 0.f), a1 = pack2(0.f, 0.f);
            a0 = fma2(w0.x, hp[0].x, a0); a1 = fma2(w0.y, hp[0].y, a1);
            a0 = fma2(w1.x, hp[1].x, a0); a1 = fma2(w1.y, hp[1].y, a1);
            a0 = fma2(w2.x, hp[2].x, a0); a1 = fma2(w2.y, hp[2].y, a1);
            a0 = fma2(w3.x, hp[3].x, a0); a1 = fma2(w3.y, hp[3].y, a1);
            float s0, s1;
            unpack2(add2(a0, a1), s0, s1);
            actb[(t0 + k) * Asz + lane] = s0 + s1;
        }
        if (lane < 8) {
            const int s = t0 + lane;
            const float* hrow = &hring[e][s & 15][0];
            float acc = bcr;
#pragma unroll
            for (int k = 0; k < 16; k++) acc = fmaf(hrow[k], wc_s[k], acc);
            crb[s] = acc;
        }
    } else if (hi) {
        hT[b * Hsz + j] = h2;
        cT[b * Hsz + j] = c;
    }
}

extern "C" void kernel_launch(void* const* d_in, const int* in_sizes, int n_in,
                              void* d_out, int out_size) {
    const float* xin      = (const float*)d_in[0];
    const float* masks    = (const float*)d_in[1];
    const float* h0       = (const float*)d_in[2];
    const float* c0       = (const float*)d_in[3];
    const float* w_ih     = (const float*)d_in[4];
    const float* w_hh     = (const float*)d_in[5];
    const float* b_ih     = (const float*)d_in[6];
    const float* b_hh     = (const float*)d_in[7];
    const float* w_actor  = (const float*)d_in[8];
    const float* b_actor  = (const float*)d_in[9];
    const float* w_critic = (const float*)d_in[10];
    const float* b_critic = (const float*)d_in[11];

    float* out    = (float*)d_out;
    float* actor  = out;
    float* critic = actor + (size_t)Bsz * Tsz * Asz;
    float* hT     = critic + (size_t)Bsz * Tsz;
    float* cT     = hT + (size_t)Bsz * Hsz;

    lstm_ws_kernel<<<Bsz / 2, 128>>>(
        xin, masks, h0, c0, w_ih, w_hh, b_ih, b_hh,
        w_actor, b_actor, w_critic, b_critic,
        actor, critic, hT, cT);
}

// round 5
// speedup vs baseline: 2.4466x; 2.4466x over previous
#include <cuda_runtime.h>
#include <cstdint>

#define Bsz 2048
#define Tsz 512
#define Asz 32
#define Hsz 16

typedef unsigned long long u64;
typedef unsigned int u32;

// ---------------- scratch (device globals: allocation-free) ----------------
// pg layout per (b,t): 64 floats = [ (i,g) float2 x16 ][ (f,o) float2 x16 ]
__device__ float pg_scratch[(size_t)Bsz * Tsz * 64];      // 256MB
__device__ float feats_scratch[(size_t)Bsz * Tsz * Hsz];  // 64MB

// ---------------- helpers ----------------
__device__ __forceinline__ void unpack2(u64 v, float& lo, float& hi) {
    asm("mov.b64 {%0, %1}, %2;" : "=f"(lo), "=f"(hi) : "l"(v));
}
__device__ __forceinline__ u64 fma2(u64 a, u64 b, u64 c) {
    u64 d; asm("fma.rn.f32x2 %0, %1, %2, %3;" : "=l"(d) : "l"(a), "l"(b), "l"(c)); return d;
}
__device__ __forceinline__ u64 add2(u64 a, u64 b) {
    u64 d; asm("add.rn.f32x2 %0, %1, %2;" : "=l"(d) : "l"(a), "l"(b)); return d;
}
__device__ __forceinline__ float sigmoidf_(float x) {
    return __fdividef(1.0f, 1.0f + __expf(-x));
}
__device__ __forceinline__ u32 smaddr(const void* p) {
    return (u32)__cvta_generic_to_shared(p);
}
__device__ __forceinline__ void cp16(u32 s, const void* g) {
    asm volatile("cp.async.ca.shared.global [%0], [%1], 16;" :: "r"(s), "l"(g));
}
__device__ __forceinline__ void cp4(u32 s, const void* g) {
    asm volatile("cp.async.ca.shared.global [%0], [%1], 4;" :: "r"(s), "l"(g));
}
#define CP_COMMIT() asm volatile("cp.async.commit_group;" ::: "memory")
#define CP_WAIT0()  asm volatile("cp.async.wait_group 0;" ::: "memory")

// ============================================================================
// K1: pregates  pg[b,t] = x W_ih^T + b_ih + b_hh
// warp per b; halves split gates: hf=0 -> rows (j, 32+j) = (i_j, g_j)
//                                 hf=1 -> rows (16+j, 48+j) = (f_j, o_j)
// x streamed via cp.async smem chunks of 8 timesteps, lead-1 double buffer.
// ============================================================================
__global__ void __launch_bounds__(128, 4) pregate_kernel(
    const float* __restrict__ xin, const float* __restrict__ w_ih,
    const float* __restrict__ b_ih, const float* __restrict__ b_hh)
{
    __shared__ __align__(16) float xsm[4][2][8 * 32];  // [warp][buf][8 steps x A]

    const int tid = threadIdx.x;
    const int w = tid >> 5, lane = tid & 31;
    const int j = lane & 15, hf = lane >> 4;
    const int b = blockIdx.x * 4 + w;

    const int rA = hf * 16 + j;
    const int rB = 32 + hf * 16 + j;
    u64 wA[16], wB[16];
    {
        const u64* pA = (const u64*)(w_ih + rA * 32);
        const u64* pB = (const u64*)(w_ih + rB * 32);
#pragma unroll
        for (int k = 0; k < 16; k++) { wA[k] = pA[k]; wB[k] = pB[k]; }
    }
    const float bsA = b_ih[rA] + b_hh[rA];
    const float bsB = b_ih[rB] + b_hh[rB];

    const float* xb = xin + (size_t)b * Tsz * Asz;
    float2* pgw = (float2*)pg_scratch + (size_t)b * Tsz * 32 + hf * 16 + j;

    // chunk loader: chunk cc covers t in [8cc, 8cc+8) = 256 floats
    auto load_chunk = [&](int cc, int bf) {
        const float* src = xb + cc * 256;
        u32 dst = smaddr(&xsm[w][bf][0]);
        cp16(dst + lane * 16,       src + lane * 4);
        cp16(dst + lane * 16 + 512, src + lane * 4 + 128);
    };

    load_chunk(0, 0); CP_COMMIT(); CP_WAIT0(); __syncwarp();

    for (int cc = 0; cc < Tsz / 8; cc++) {
        if (cc + 1 < Tsz / 8) load_chunk(cc + 1, (cc + 1) & 1);
        CP_COMMIT();
#pragma unroll
        for (int s = 0; s < 8; s++) {
            const int t = cc * 8 + s;
            const ulonglong2* xp = (const ulonglong2*)&xsm[w][cc & 1][s * 32];
            u64 a0 = 0, a1 = 0, g0 = 0, g1 = 0;
#pragma unroll
            for (int q = 0; q < 8; q++) {
                const ulonglong2 v = xp[q];
                a0 = fma2(wA[2 * q], v.x, a0);
                a1 = fma2(wA[2 * q + 1], v.y, a1);
                g0 = fma2(wB[2 * q], v.x, g0);
                g1 = fma2(wB[2 * q + 1], v.y, g1);
            }
            float lo, hi;
            float2 o;
            unpack2(add2(a0, a1), lo, hi); o.x = lo + hi + bsA;
            unpack2(add2(g0, g1), lo, hi); o.y = lo + hi + bsB;
            pgw[t * 32] = o;
        }
        CP_WAIT0(); __syncwarp();
    }
}

// ============================================================================
// K2: recurrence. warp = 2 elements (one per half-warp).
// Lane j owns h-index j: computes i_j, f_j, g_j, o_j, c_j, h_j entirely
// in-lane (no shfl). h exchanged via per-elem smem double buffer.
// pg + masks streamed via cp.async chunks of 8 steps.
// ============================================================================
__global__ void __launch_bounds__(128, 4) recur_kernel(
    const float* __restrict__ masks, const float* __restrict__ h0,
    const float* __restrict__ c0, const float* __restrict__ w_hh,
    float* __restrict__ hT, float* __restrict__ cT)
{
    __shared__ __align__(16) float hbuf[2][8][16];
    __shared__ __align__(16) float pgsm[2][8][8 * 64];  // [buf][elem][8 steps x 64]
    __shared__ float msm[2][8][8];                      // [buf][elem][8 steps]

    const int tid = threadIdx.x;
    const int w = tid >> 5, lane = tid & 31;
    const int j = lane & 15, hf = lane >> 4;
    const int e = w * 2 + hf;
    const int b = blockIdx.x * 8 + e;

    u64 whI[8], whF[8], whG[8], whO[8];
    {
        const u64* pI = (const u64*)(w_hh + (j) * 16);
        const u64* pF = (const u64*)(w_hh + (16 + j) * 16);
        const u64* pG = (const u64*)(w_hh + (32 + j) * 16);
        const u64* pO = (const u64*)(w_hh + (48 + j) * 16);
#pragma unroll
        for (int k = 0; k < 8; k++) {
            whI[k] = pI[k]; whF[k] = pF[k]; whG[k] = pG[k]; whO[k] = pO[k];
        }
    }

    float c  = c0[b * Hsz + j];
    float h2 = h0[b * Hsz + j];
    hbuf[0][e][j] = h2;

    const float* mb  = masks + (size_t)b * Tsz;
    const float* pgb = pg_scratch + (size_t)b * Tsz * 64;
    float* fb        = feats_scratch + (size_t)b * Tsz * Hsz;

    // chunk loader: each half-warp loads its own elem's 8 steps (512 floats)
    auto load_chunk = [&](int cc, int bf) {
        const float4* src = (const float4*)(pgb + (size_t)cc * 8 * 64);
        u32 dst = smaddr(&pgsm[bf][e][0]);
#pragma unroll
        for (int q = 0; q < 8; q++)
            cp16(dst + (j + q * 16) * 16, src + j + q * 16);
        if (j < 8) cp4(smaddr(&msm[bf][e][j]), mb + cc * 8 + j);
    };

    load_chunk(0, 0); CP_COMMIT(); CP_WAIT0(); __syncwarp();

    for (int cc = 0; cc < Tsz / 8; cc++) {
        if (cc + 1 < Tsz / 8) load_chunk(cc + 1, (cc + 1) & 1);
        CP_COMMIT();
#pragma unroll
        for (int s = 0; s < 8; s++) {
            const int t = cc * 8 + s;
            // h_{t-1}: 16 floats broadcast within half-warp
            const ulonglong2* hp = (const ulonglong2*)&hbuf[t & 1][e][0];
            u64 hv[8];
#pragma unroll
            for (int q = 0; q < 4; q++) {
                const ulonglong2 v = hp[q];
                hv[2 * q] = v.x; hv[2 * q + 1] = v.y;
            }
            u64 aI = 0, aF = 0, aG = 0, aO = 0;
#pragma unroll
            for (int k = 0; k < 8; k++) {
                aI = fma2(whI[k], hv[k], aI);
                aF = fma2(whF[k], hv[k], aF);
                aG = fma2(whG[k], hv[k], aG);
                aO = fma2(whO[k], hv[k], aO);
            }
            float lo, hi;
            unpack2(aI, lo, hi); const float sI = lo + hi;
            unpack2(aF, lo, hi); const float sF = lo + hi;
            unpack2(aG, lo, hi); const float sG = lo + hi;
            unpack2(aO, lo, hi); const float sO = lo + hi;

            const float2 pIG = *(const float2*)&pgsm[cc & 1][e][s * 64 + 2 * j];
            const float2 pFO = *(const float2*)&pgsm[cc & 1][e][s * 64 + 32 + 2 * j];
            const float m = msm[cc & 1][e][s];

            const float gI = fmaf(m, sI, pIG.x);
            const float gG = fmaf(m, sG, pIG.y);
            const float gF = fmaf(m, sF, pFO.x);
            const float gO = fmaf(m, sO, pFO.y);

            const float vI = sigmoidf_(gI);
            const float vF = sigmoidf_(gF);
            const float vO = sigmoidf_(gO);
            const float vG = fmaf(2.0f, sigmoidf_(2.0f * gG), -1.0f); // tanh

            c  = fmaf(vF, c * m, vI * vG);
            h2 = vO * fmaf(2.0f, sigmoidf_(2.0f * c), -1.0f);

            fb[t * Hsz + j] = h2;            // feats output
            hbuf[(t + 1) & 1][e][j] = h2;    // next step's h
            __syncwarp();
        }
        CP_WAIT0(); __syncwarp();
    }

    hT[b * Hsz + j] = h2;
    cT[b * Hsz + j] = c;
}

// ============================================================================
// K3a: actor head. warp per (b, 128-step chunk); lane = actor row.
// ============================================================================
__global__ void __launch_bounds__(128) actor_kernel(
    const float* __restrict__ w_actor, const float* __restrict__ b_actor,
    float* __restrict__ actor)
{
    const int tid = threadIdx.x;
    const int w = tid >> 5, lane = tid & 31;
    const int widx = blockIdx.x * 4 + w;
    const int b = widx >> 2;
    const int t0 = (widx & 3) * 128;

    u64 wr[8];
    {
        const u64* p = (const u64*)(w_actor + lane * 16);
#pragma unroll
        for (int k = 0; k < 8; k++) wr[k] = p[k];
    }
    const float bias = b_actor[lane];

    const float* fb = feats_scratch + ((size_t)b * Tsz + t0) * Hsz;
    float* ab       = actor + ((size_t)b * Tsz + t0) * Asz;

    u64 v0[8], v1[8];
#pragma unroll
    for (int q = 0; q < 4; q++) {
        ulonglong2 a = ((const ulonglong2*)(fb))[q];
        ulonglong2 c = ((const ulonglong2*)(fb + Hsz))[q];
        v0[2 * q] = a.x; v0[2 * q + 1] = a.y;
        v1[2 * q] = c.x; v1[2 * q + 1] = c.y;
    }

#pragma unroll 4
    for (int i = 0; i < 128; i++) {
        const int ip = (i + 2 < 128) ? i + 2 : 127;
        u64 vn[8];
#pragma unroll
        for (int q = 0; q < 4; q++) {
            ulonglong2 a = ((const ulonglong2*)(fb + ip * Hsz))[q];
            vn[2 * q] = a.x; vn[2 * q + 1] = a.y;
        }
        u64 a0 = 0, a1 = 0;
#pragma unroll
        for (int k = 0; k < 4; k++) {
            a0 = fma2(wr[2 * k], v0[2 * k], a0);
            a1 = fma2(wr[2 * k + 1], v0[2 * k + 1], a1);
        }
        float lo, hi;
        unpack2(add2(a0, a1), lo, hi);
        ab[i * Asz + lane] = lo + hi + bias;
#pragma unroll
        for (int k = 0; k < 8; k++) { v0[k] = v1[k]; v1[k] = vn[k]; }
    }
}

// ============================================================================
// K3b: critic head. thread per (b,t).
// ============================================================================
__global__ void __launch_bounds__(128) critic_kernel(
    const float* __restrict__ w_critic, const float* __restrict__ b_critic,
    float* __restrict__ critic)
{
    const size_t idx = (size_t)blockIdx.x * 128 + threadIdx.x;
    u64 wc[8];
    {
        const u64* p = (const u64*)w_critic;
#pragma unroll
        for (int k = 0; k < 8; k++) wc[k] = p[k];
    }
    const u64* fp = (const u64*)(feats_scratch + idx * Hsz);
    u64 a0 = 0, a1 = 0;
#pragma unroll
    for (int k = 0; k < 4; k++) {
        a0 = fma2(wc[2 * k], fp[2 * k], a0);
        a1 = fma2(wc[2 * k + 1], fp[2 * k + 1], a1);
    }
    float lo, hi;
    unpack2(add2(a0, a1), lo, hi);
    critic[idx] = lo + hi + b_critic[0];
}

// ============================================================================
extern "C" void kernel_launch(void* const* d_in, const int* in_sizes, int n_in,
                              void* d_out, int out_size) {
    const float* xin      = (const float*)d_in[0];
    const float* masks    = (const float*)d_in[1];
    const float* h0       = (const float*)d_in[2];
    const float* c0       = (const float*)d_in[3];
    const float* w_ih     = (const float*)d_in[4];
    const float* w_hh     = (const float*)d_in[5];
    const float* b_ih     = (const float*)d_in[6];
    const float* b_hh     = (const float*)d_in[7];
    const float* w_actor  = (const float*)d_in[8];
    const float* b_actor  = (const float*)d_in[9];
    const float* w_critic = (const float*)d_in[10];
    const float* b_critic = (const float*)d_in[11];

    float* out    = (float*)d_out;
    float* actor  = out;
    float* critic = actor + (size_t)Bsz * Tsz * Asz;
    float* hT     = critic + (size_t)Bsz * Tsz;
    float* cT     = hT + (size_t)Bsz * Hsz;

    pregate_kernel<<<Bsz / 4, 128>>>(xin, w_ih, b_ih, b_hh);
    recur_kernel<<<Bsz / 8, 128>>>(masks, h0, c0, w_hh, hT, cT);
    actor_kernel<<<(Bsz * 4) / 4, 128>>>(w_actor, b_actor, actor);
    critic_kernel<<<(Bsz * Tsz) / 128, 128>>>(w_critic, b_critic, critic);
}

// round 6
// speedup vs baseline: 2.7422x; 1.1208x over previous
#include <cuda_runtime.h>
#include <cstdint>

#define Bsz 2048
#define Tsz 512
#define Asz 32
#define Hsz 16

typedef unsigned long long u64;
typedef unsigned int u32;

// pg layout per (b,t): 32 float2 = [ (i_j,g_j) j=0..15 ][ (f_j,o_j) j=0..15 ]
__device__ float pg_scratch[(size_t)Bsz * Tsz * 64];   // 256MB

__device__ __forceinline__ void unpack2(u64 v, float& lo, float& hi) {
    asm("mov.b64 {%0, %1}, %2;" : "=f"(lo), "=f"(hi) : "l"(v));
}
__device__ __forceinline__ u64 fma2(u64 a, u64 b, u64 c) {
    u64 d; asm("fma.rn.f32x2 %0, %1, %2, %3;" : "=l"(d) : "l"(a), "l"(b), "l"(c)); return d;
}
__device__ __forceinline__ u64 add2(u64 a, u64 b) {
    u64 d; asm("add.rn.f32x2 %0, %1, %2;" : "=l"(d) : "l"(a), "l"(b)); return d;
}
__device__ __forceinline__ float sigmoidf_(float x) {
    return __fdividef(1.0f, 1.0f + __expf(-x));
}
__device__ __forceinline__ u32 smaddr(const void* p) {
    return (u32)__cvta_generic_to_shared(p);
}
__device__ __forceinline__ void cp16(u32 s, const void* g) {
    asm volatile("cp.async.ca.shared.global [%0], [%1], 16;" :: "r"(s), "l"(g));
}
__device__ __forceinline__ void cp4(u32 s, const void* g) {
    asm volatile("cp.async.ca.shared.global [%0], [%1], 4;" :: "r"(s), "l"(g));
}
#define CP_COMMIT() asm volatile("cp.async.commit_group;" ::: "memory")
#define CP_WAIT0()  asm volatile("cp.async.wait_group 0;" ::: "memory")

// ============================================================================
// K1: pregates  pg[b,t] = x W_ih^T + b_ih + b_hh   (unchanged from R5)
// warp per b; lane = hf*16+j computes rows (hf*16+j, 32+hf*16+j).
// ============================================================================
__global__ void __launch_bounds__(128, 4) pregate_kernel(
    const float* __restrict__ xin, const float* __restrict__ w_ih,
    const float* __restrict__ b_ih, const float* __restrict__ b_hh)
{
    __shared__ __align__(16) float xsm[4][2][8 * 32];

    const int tid = threadIdx.x;
    const int w = tid >> 5, lane = tid & 31;
    const int b = blockIdx.x * 4 + w;

    const int rA = lane;
    const int rB = 32 + lane;
    u64 wA[16], wB[16];
    {
        const u64* pA = (const u64*)(w_ih + rA * 32);
        const u64* pB = (const u64*)(w_ih + rB * 32);
#pragma unroll
        for (int k = 0; k < 16; k++) { wA[k] = pA[k]; wB[k] = pB[k]; }
    }
    const float bsA = b_ih[rA] + b_hh[rA];
    const float bsB = b_ih[rB] + b_hh[rB];

    const float* xb = xin + (size_t)b * Tsz * Asz;
    float2* pgw = (float2*)pg_scratch + (size_t)b * Tsz * 32 + lane;

    auto load_chunk = [&](int cc, int bf) {
        const float* src = xb + cc * 256;
        u32 dst = smaddr(&xsm[w][bf][0]);
        cp16(dst + lane * 16,       src + lane * 4);
        cp16(dst + lane * 16 + 512, src + lane * 4 + 128);
    };

    load_chunk(0, 0); CP_COMMIT(); CP_WAIT0(); __syncwarp();

    for (int cc = 0; cc < Tsz / 8; cc++) {
        if (cc + 1 < Tsz / 8) load_chunk(cc + 1, (cc + 1) & 1);
        CP_COMMIT();
#pragma unroll
        for (int s = 0; s < 8; s++) {
            const int t = cc * 8 + s;
            const ulonglong2* xp = (const ulonglong2*)&xsm[w][cc & 1][s * 32];
            u64 a0 = 0, a1 = 0, g0 = 0, g1 = 0;
#pragma unroll
            for (int q = 0; q < 8; q++) {
                const ulonglong2 v = xp[q];
                a0 = fma2(wA[2 * q], v.x, a0);
                a1 = fma2(wA[2 * q + 1], v.y, a1);
                g0 = fma2(wB[2 * q], v.x, g0);
                g1 = fma2(wB[2 * q + 1], v.y, g1);
            }
            float lo, hi;
            float2 o;
            unpack2(add2(a0, a1), lo, hi); o.x = lo + hi + bsA;
            unpack2(add2(g0, g1), lo, hi); o.y = lo + hi + bsB;
            pgw[t * 32] = o;
        }
        CP_WAIT0(); __syncwarp();
    }
}

// ============================================================================
// K2: recurrence + FUSED actor/critic heads. One element per warp.
//   lane j   (lo): gates (i_j, g_j) via w_hh rows j,    32+j
//   lane 16+j(hi): gates (f_j, o_j) via w_hh rows 16+j, 48+j; owns c_j, h_j
// h exchanged via smem double buffer (broadcast reads). Every lane holds the
// full h_t vector at step t+1, so actor (lane = output row) and critic
// (in-lane dot) for step t are computed from registers — no feats scratch.
// ============================================================================
__global__ void __launch_bounds__(128, 4) recur_heads_kernel(
    const float* __restrict__ masks, const float* __restrict__ h0,
    const float* __restrict__ c0, const float* __restrict__ w_hh,
    const float* __restrict__ w_actor, const float* __restrict__ b_actor,
    const float* __restrict__ w_critic, const float* __restrict__ b_critic,
    float* __restrict__ actor, float* __restrict__ critic,
    float* __restrict__ hT, float* __restrict__ cT)
{
    __shared__ __align__(16) float hbuf[4][2][16];
    __shared__ __align__(16) float pgsm[4][2][8 * 64];
    __shared__ float msm[4][2][8];

    const int tid = threadIdx.x;
    const int w = tid >> 5, lane = tid & 31;
    const int j = lane & 15;
    const bool hi_half = lane >= 16;
    const int b = blockIdx.x * 4 + w;

    // h-part weights: rowP = lane, rowQ = 32+lane (torch gate order i,f,g,o)
    u64 whP[8], whQ[8];
    {
        const u64* pP = (const u64*)(w_hh + lane * 16);
        const u64* pQ = (const u64*)(w_hh + (32 + lane) * 16);
#pragma unroll
        for (int k = 0; k < 8; k++) { whP[k] = pP[k]; whQ[k] = pQ[k]; }
    }
    // head weights
    u64 wact[8], wcr[8];
    {
        const u64* pa = (const u64*)(w_actor + lane * 16);
        const u64* pc = (const u64*)w_critic;
#pragma unroll
        for (int k = 0; k < 8; k++) { wact[k] = pa[k]; wcr[k] = pc[k]; }
    }
    const float bact = b_actor[lane];
    const float bcr  = b_critic[0];

    float c = c0[b * Hsz + j];
    if (lane < 16) hbuf[w][0][lane] = h0[b * Hsz + lane];

    const float* mb  = masks + (size_t)b * Tsz;
    const float* pgb = pg_scratch + (size_t)b * Tsz * 64;
    float* actb      = actor + (size_t)b * Tsz * Asz;
    float* crb       = critic + (size_t)b * Tsz;

    auto load_chunk = [&](int cc, int bf) {
        const float4* src = (const float4*)(pgb + (size_t)cc * 8 * 64);
        u32 dst = smaddr(&pgsm[w][bf][0]);
#pragma unroll
        for (int q = 0; q < 4; q++)
            cp16(dst + (lane + q * 32) * 16, src + lane + q * 32);
        if (lane < 8) cp4(smaddr(&msm[w][bf][lane]), mb + cc * 8 + lane);
    };

    load_chunk(0, 0); CP_COMMIT(); CP_WAIT0(); __syncwarp();

    float h2 = 0.0f;

    for (int cc = 0; cc < Tsz / 8; cc++) {
        if (cc + 1 < Tsz / 8) load_chunk(cc + 1, (cc + 1) & 1);
        CP_COMMIT();
#pragma unroll
        for (int s = 0; s < 8; s++) {
            const int t = cc * 8 + s;
            // hv = h_{t-1}, broadcast from smem
            u64 hv[8];
            {
                const ulonglong2* hp = (const ulonglong2*)&hbuf[w][t & 1][0];
#pragma unroll
                for (int q = 0; q < 4; q++) {
                    const ulonglong2 v = hp[q];
                    hv[2 * q] = v.x; hv[2 * q + 1] = v.y;
                }
            }
            // ---- heads for step t-1 (hv == h_{t-1})
            if (t > 0) {
                u64 aa = 0, ca = 0;
#pragma unroll
                for (int k = 0; k < 8; k++) {
                    aa = fma2(wact[k], hv[k], aa);
                    ca = fma2(wcr[k],  hv[k], ca);
                }
                float lo, hi;
                unpack2(aa, lo, hi);
                actb[(t - 1) * Asz + lane] = lo + hi + bact;
                unpack2(ca, lo, hi);
                if (lane == 0) crb[t - 1] = lo + hi + bcr;
            }
            // ---- gates
            u64 aP = 0, aQ = 0;
#pragma unroll
            for (int k = 0; k < 8; k++) {
                aP = fma2(whP[k], hv[k], aP);
                aQ = fma2(whQ[k], hv[k], aQ);
            }
            float lo, hi;
            unpack2(aP, lo, hi); const float sP = lo + hi;
            unpack2(aQ, lo, hi); const float sQ = lo + hi;

            const float2 pgv = *(const float2*)&pgsm[w][cc & 1][s * 64 + 2 * lane];
            const float m = msm[w][cc & 1][s];

            const float gP = fmaf(m, sP, pgv.x);   // lo: i, hi: f
            const float gQ = fmaf(m, sQ, pgv.y);   // lo: g, hi: o

            const float vP = sigmoidf_(gP);
            const float sgQ = sigmoidf_(hi_half ? gQ : 2.0f * gQ);
            const float vQ = hi_half ? sgQ : fmaf(2.0f, sgQ, -1.0f);  // tanh for g

            const float p  = vP * vQ;                          // lo: i*g
            const float ig = __shfl_sync(0xffffffffu, p, j);   // hi fetches i*g

            c  = fmaf(vP, c * m, ig);                          // hi: c2 = f*(c*m)+i*g
            h2 = vQ * fmaf(2.0f, sigmoidf_(2.0f * c), -1.0f);  // hi: o*tanh(c2)

            if (hi_half) hbuf[w][(t + 1) & 1][j] = h2;
            __syncwarp();
        }
        CP_WAIT0(); __syncwarp();
    }

    // tail: heads for t = Tsz-1 using final h (buf index Tsz&1 == 0)
    {
        u64 hv[8];
        const ulonglong2* hp = (const ulonglong2*)&hbuf[w][Tsz & 1][0];
#pragma unroll
        for (int q = 0; q < 4; q++) {
            const ulonglong2 v = hp[q];
            hv[2 * q] = v.x; hv[2 * q + 1] = v.y;
        }
        u64 aa = 0, ca = 0;
#pragma unroll
        for (int k = 0; k < 8; k++) {
            aa = fma2(wact[k], hv[k], aa);
            ca = fma2(wcr[k],  hv[k], ca);
        }
        float lo, hi;
        unpack2(aa, lo, hi);
        actb[(Tsz - 1) * Asz + lane] = lo + hi + bact;
        unpack2(ca, lo, hi);
        if (lane == 0) crb[Tsz - 1] = lo + hi + bcr;
    }

    if (hi_half) {
        hT[b * Hsz + j] = h2;
        cT[b * Hsz + j] = c;
    }
}

// ============================================================================
extern "C" void kernel_launch(void* const* d_in, const int* in_sizes, int n_in,
                              void* d_out, int out_size) {
    const float* xin      = (const float*)d_in[0];
    const float* masks    = (const float*)d_in[1];
    const float* h0       = (const float*)d_in[2];
    const float* c0       = (const float*)d_in[3];
    const float* w_ih     = (const float*)d_in[4];
    const float* w_hh     = (const float*)d_in[5];
    const float* b_ih     = (const float*)d_in[6];
    const float* b_hh     = (const float*)d_in[7];
    const float* w_actor  = (const float*)d_in[8];
    const float* b_actor  = (const float*)d_in[9];
    const float* w_critic = (const float*)d_in[10];
    const float* b_critic = (const float*)d_in[11];

    float* out    = (float*)d_out;
    float* actor  = out;
    float* critic = actor + (size_t)Bsz * Tsz * Asz;
    float* hT     = critic + (size_t)Bsz * Tsz;
    float* cT     = hT + (size_t)Bsz * Hsz;

    pregate_kernel<<<Bsz / 4, 128>>>(xin, w_ih, b_ih, b_hh);
    recur_heads_kernel<<<Bsz / 4, 128>>>(masks, h0, c0, w_hh,
                                         w_actor, b_actor, w_critic, b_critic,
                                         actor, critic, hT, cT);
}

// round 7
// speedup vs baseline: 2.8370x; 1.0346x over previous
#include <cuda_runtime.h>
#include <cstdint>

#define Bsz 2048
#define Tsz 512
#define Asz 32
#define Hsz 16
#define NCHUNK (Tsz / 8)

typedef unsigned long long u64;
typedef unsigned int u32;

__device__ __forceinline__ void unpack2(u64 v, float& lo, float& hi) {
    asm("mov.b64 {%0, %1}, %2;" : "=f"(lo), "=f"(hi) : "l"(v));
}
__device__ __forceinline__ u64 fma2(u64 a, u64 b, u64 c) {
    u64 d; asm("fma.rn.f32x2 %0, %1, %2, %3;" : "=l"(d) : "l"(a), "l"(b), "l"(c)); return d;
}
__device__ __forceinline__ u64 add2(u64 a, u64 b) {
    u64 d; asm("add.rn.f32x2 %0, %1, %2;" : "=l"(d) : "l"(a), "l"(b)); return d;
}
__device__ __forceinline__ float hsum2(u64 v) {
    float lo, hi; unpack2(v, lo, hi); return lo + hi;
}
__device__ __forceinline__ float sigmoidf_(float x) {
    return __fdividef(1.0f, 1.0f + __expf(-x));
}
__device__ __forceinline__ u32 smaddr(const void* p) {
    return (u32)__cvta_generic_to_shared(p);
}
__device__ __forceinline__ void cp16(u32 s, const void* g) {
    asm volatile("cp.async.ca.shared.global [%0], [%1], 16;" :: "r"(s), "l"(g));
}
#define CP_COMMIT() asm volatile("cp.async.commit_group;" ::: "memory")
#define CP_WAIT1()  asm volatile("cp.async.wait_group 1;" ::: "memory")

// ============================================================================
// Fused LSTM: CTA = 64 threads = 2 warps = 2 batch elements.
//   warp 0 (consumer): recurrence + actor/critic heads. Half-warp per element;
//                      lane j owns h-index j and computes ALL 4 gates in-lane
//                      (no shfl on the c critical path).
//   warp 1 (producer): pregates pg = x W_ih^T + b for BOTH elements, one chunk
//                      (8 steps) ahead, x streamed via cp.async double buffer.
// pg ring in SMEM (2 chunks deep) — never touches HBM. One __syncthreads per
// chunk orders producer fill vs consumer read.
// ============================================================================
__global__ void __launch_bounds__(64, 6) lstm_fused(
    const float* __restrict__ xin, const float* __restrict__ masks,
    const float* __restrict__ h0, const float* __restrict__ c0,
    const float* __restrict__ w_ih, const float* __restrict__ w_hh,
    const float* __restrict__ b_ih, const float* __restrict__ b_hh,
    const float* __restrict__ w_actor, const float* __restrict__ b_actor,
    const float* __restrict__ w_critic, const float* __restrict__ b_critic,
    float* __restrict__ actor, float* __restrict__ critic,
    float* __restrict__ hT, float* __restrict__ cT)
{
    // pg layout per (elem, buf, step): 32 float2 pairs: [2p] = (row p, row 32+p)
    __shared__ __align__(16) float pgsm[2][2][8 * 64];
    __shared__ __align__(16) float xsm[2][2][8 * 32];
    __shared__ __align__(16) float hbuf[2][2][16];

    const int tid  = threadIdx.x;
    const int w    = tid >> 5;
    const int lane = tid & 31;
    const int b0   = blockIdx.x * 2;

    if (w == 1) {
        // ---------------- PRODUCER ----------------
        const int p = lane;                       // gate rows p and 32+p
        u64 wA[16], wB[16];
        {
            const u64* pA = (const u64*)(w_ih + p * 32);
            const u64* pB = (const u64*)(w_ih + (32 + p) * 32);
#pragma unroll
            for (int k = 0; k < 16; k++) { wA[k] = pA[k]; wB[k] = pB[k]; }
        }
        const float bsA = b_ih[p] + b_hh[p];
        const float bsB = b_ih[32 + p] + b_hh[32 + p];
        const float* xb0 = xin + (size_t)b0 * Tsz * Asz;
        const float* xb1 = xin + (size_t)(b0 + 1) * Tsz * Asz;

        auto loadx = [&](int ch) {
            const int bf = ch & 1;
            u32 d0 = smaddr(&xsm[0][bf][0]);
            u32 d1 = smaddr(&xsm[1][bf][0]);
            const float* s0 = xb0 + ch * 256;
            const float* s1 = xb1 + ch * 256;
            cp16(d0 + lane * 16,       s0 + lane * 4);
            cp16(d0 + lane * 16 + 512, s0 + lane * 4 + 128);
            cp16(d1 + lane * 16,       s1 + lane * 4);
            cp16(d1 + lane * 16 + 512, s1 + lane * 4 + 128);
        };
        auto comp = [&](int ch) {
            const int bf = ch & 1;
#pragma unroll
            for (int e = 0; e < 2; e++) {
#pragma unroll
                for (int s = 0; s < 8; s++) {
                    const ulonglong2* xp = (const ulonglong2*)&xsm[e][bf][s * 32];
                    u64 a0 = 0, a1 = 0, g0 = 0, g1 = 0;
#pragma unroll
                    for (int q = 0; q < 8; q++) {
                        const ulonglong2 v = xp[q];
                        a0 = fma2(wA[2 * q],     v.x, a0);
                        a1 = fma2(wA[2 * q + 1], v.y, a1);
                        g0 = fma2(wB[2 * q],     v.x, g0);
                        g1 = fma2(wB[2 * q + 1], v.y, g1);
                    }
                    float2 o;
                    o.x = hsum2(add2(a0, a1)) + bsA;
                    o.y = hsum2(add2(g0, g1)) + bsB;
                    *(float2*)&pgsm[e][bf][s * 64 + 2 * lane] = o;
                }
            }
        };

        loadx(0); CP_COMMIT();
        loadx(1); CP_COMMIT();
        CP_WAIT1();
        comp(0);
        __syncthreads();                          // pg chunk 0 ready

        for (int cc = 0; cc < NCHUNK; cc++) {
            if (cc + 2 < NCHUNK) loadx(cc + 2);
            CP_COMMIT();
            CP_WAIT1();                           // x_{cc+1} landed
            if (cc + 1 < NCHUNK) comp(cc + 1);
            __syncthreads();
        }
    } else {
        // ---------------- CONSUMER ----------------
        const int e = lane >> 4;                  // element within CTA
        const int j = lane & 15;                  // h index
        const int b = b0 + e;

        u64 whI[8], whF[8], whG[8], whO[8];
        {
            const u64* pI = (const u64*)(w_hh + j * 16);
            const u64* pF = (const u64*)(w_hh + (16 + j) * 16);
            const u64* pG = (const u64*)(w_hh + (32 + j) * 16);
            const u64* pO = (const u64*)(w_hh + (48 + j) * 16);
#pragma unroll
            for (int k = 0; k < 8; k++) {
                whI[k] = pI[k]; whF[k] = pF[k]; whG[k] = pG[k]; whO[k] = pO[k];
            }
        }
        u64 wa0[8], wa1[8];                       // actor rows 2j, 2j+1
        {
            const u64* p0 = (const u64*)(w_actor + (2 * j) * 16);
            const u64* p1 = (const u64*)(w_actor + (2 * j + 1) * 16);
#pragma unroll
            for (int k = 0; k < 8; k++) { wa0[k] = p0[k]; wa1[k] = p1[k]; }
        }
        const float bact0 = b_actor[2 * j];
        const float bact1 = b_actor[2 * j + 1];
        const float wcj   = w_critic[j];
        const float bcr   = b_critic[0];

        const float* mb = masks + (size_t)b * Tsz;
        float* actb     = actor + (size_t)b * Tsz * Asz;
        float* crb      = critic + (size_t)b * Tsz;

        float c  = c0[b * Hsz + j];
        hbuf[e][0][j] = h0[b * Hsz + j];
        float m_cur = mb[0];
        float h2 = 0.0f;

        __syncthreads();                          // match producer prologue

        for (int cc = 0; cc < NCHUNK; cc++) {
#pragma unroll
            for (int s = 0; s < 8; s++) {
                const int t = cc * 8 + s;
                const float m = m_cur;
                m_cur = mb[(t + 1 < Tsz) ? t + 1 : Tsz - 1];   // prefetch

                // hv = h_{t-1} (broadcast within half-warp)
                u64 hv[8];
                {
                    const ulonglong2* hp = (const ulonglong2*)&hbuf[e][t & 1][0];
#pragma unroll
                    for (int q = 0; q < 4; q++) {
                        const ulonglong2 v = hp[q];
                        hv[2 * q] = v.x; hv[2 * q + 1] = v.y;
                    }
                }
                const float hj = hbuf[e][t & 1][j];

                // ---- heads for step t-1 (use h_{t-1})
                if (t > 0) {
                    u64 A0 = 0, A1 = 0, B0 = 0, B1 = 0;
#pragma unroll
                    for (int k = 0; k < 4; k++) {
                        A0 = fma2(wa0[2 * k],     hv[2 * k],     A0);
                        A1 = fma2(wa0[2 * k + 1], hv[2 * k + 1], A1);
                        B0 = fma2(wa1[2 * k],     hv[2 * k],     B0);
                        B1 = fma2(wa1[2 * k + 1], hv[2 * k + 1], B1);
                    }
                    float2 av;
                    av.x = hsum2(add2(A0, A1)) + bact0;
                    av.y = hsum2(add2(B0, B1)) + bact1;
                    *(float2*)&actb[(t - 1) * Asz + 2 * j] = av;

                    float cp = hj * wcj;
                    cp += __shfl_xor_sync(0xffffffffu, cp, 8);
                    cp += __shfl_xor_sync(0xffffffffu, cp, 4);
                    cp += __shfl_xor_sync(0xffffffffu, cp, 2);
                    cp += __shfl_xor_sync(0xffffffffu, cp, 1);
                    if (j == 0) crb[t - 1] = cp + bcr;
                }

                // ---- gates (all four in-lane)
                u64 aI = 0, aF = 0, aG = 0, aO = 0;
#pragma unroll
                for (int k = 0; k < 8; k++) {
                    aI = fma2(whI[k], hv[k], aI);
                    aF = fma2(whF[k], hv[k], aF);
                    aG = fma2(whG[k], hv[k], aG);
                    aO = fma2(whO[k], hv[k], aO);
                }
                const float sI = hsum2(aI), sF = hsum2(aF);
                const float sG = hsum2(aG), sO = hsum2(aO);

                const float2 pIG = *(const float2*)&pgsm[e][cc & 1][s * 64 + 2 * j];
                const float2 pFO = *(const float2*)&pgsm[e][cc & 1][s * 64 + 32 + 2 * j];

                const float gI = fmaf(m, sI, pIG.x);
                const float gG = fmaf(m, sG, pIG.y);
                const float gF = fmaf(m, sF, pFO.x);
                const float gO = fmaf(m, sO, pFO.y);

                const float vI = sigmoidf_(gI);
                const float vF = sigmoidf_(gF);
                const float vO = sigmoidf_(gO);
                const float vG = fmaf(2.0f, sigmoidf_(2.0f * gG), -1.0f); // tanh

                c  = fmaf(vF, c * m, vI * vG);
                h2 = vO * fmaf(2.0f, sigmoidf_(2.0f * c), -1.0f);

                hbuf[e][(t + 1) & 1][j] = h2;
                __syncwarp();
            }
            __syncthreads();
        }

        // ---- tail heads for t = Tsz-1 (h_511 in hbuf[e][0])
        {
            u64 hv[8];
            const ulonglong2* hp = (const ulonglong2*)&hbuf[e][Tsz & 1][0];
#pragma unroll
            for (int q = 0; q < 4; q++) {
                const ulonglong2 v = hp[q];
                hv[2 * q] = v.x; hv[2 * q + 1] = v.y;
            }
            u64 A0 = 0, A1 = 0, B0 = 0, B1 = 0;
#pragma unroll
            for (int k = 0; k < 4; k++) {
                A0 = fma2(wa0[2 * k],     hv[2 * k],     A0);
                A1 = fma2(wa0[2 * k + 1], hv[2 * k + 1], A1);
                B0 = fma2(wa1[2 * k],     hv[2 * k],     B0);
                B1 = fma2(wa1[2 * k + 1], hv[2 * k + 1], B1);
            }
            float2 av;
            av.x = hsum2(add2(A0, A1)) + bact0;
            av.y = hsum2(add2(B0, B1)) + bact1;
            *(float2*)&actb[(Tsz - 1) * Asz + 2 * j] = av;

            float cp = h2 * wcj;
            cp += __shfl_xor_sync(0xffffffffu, cp, 8);
            cp += __shfl_xor_sync(0xffffffffu, cp, 4);
            cp += __shfl_xor_sync(0xffffffffu, cp, 2);
            cp += __shfl_xor_sync(0xffffffffu, cp, 1);
            if (j == 0) crb[Tsz - 1] = cp + bcr;
        }

        hT[b * Hsz + j] = h2;
        cT[b * Hsz + j] = c;
    }
}

extern "C" void kernel_launch(void* const* d_in, const int* in_sizes, int n_in,
                              void* d_out, int out_size) {
    const float* xin      = (const float*)d_in[0];
    const float* masks    = (const float*)d_in[1];
    const float* h0       = (const float*)d_in[2];
    const float* c0       = (const float*)d_in[3];
    const float* w_ih     = (const float*)d_in[4];
    const float* w_hh     = (const float*)d_in[5];
    const float* b_ih     = (const float*)d_in[6];
    const float* b_hh     = (const float*)d_in[7];
    const float* w_actor  = (const float*)d_in[8];
    const float* b_actor  = (const float*)d_in[9];
    const float* w_critic = (const float*)d_in[10];
    const float* b_critic = (const float*)d_in[11];

    float* out    = (float*)d_out;
    float* actor  = out;
    float* critic = actor + (size_t)Bsz * Tsz * Asz;
    float* hT     = critic + (size_t)Bsz * Tsz;
    float* cT     = hT + (size_t)Bsz * Hsz;

    lstm_fused<<<Bsz / 2, 64>>>(xin, masks, h0, c0, w_ih, w_hh, b_ih, b_hh,
                                w_actor, b_actor, w_critic, b_critic,
                                actor, critic, hT, cT);
}